// round 17
// baseline (speedup 1.0000x reference)
#include <cuda_runtime.h>
#include <cstdint>

// CTC batch cost (Keras ctc_batch_cost), blank = V-1.
// B=256, T=512, V=256, L=64, S=129.
//
// R17: two elements per CTA (128 CTAs, 128 thr: warps 0/1 consumers, 2/3
// producers, per-pair named barriers). Producer now loads ONLY the sectors
// the DP needs: a warp-wide 32-bit mask of needed 32B sectors (labels +
// blank) is compacted; lane k streams the k-th needed sector of every row
// via 2x16B cp.async (ring: 8 chunks x 8 rows). The conflicted gather into
// the compact (q1,q3,blank) buffer uses popcount-remapped offsets. Barrier
// cadence halved: one bar per 2 chunks, 4 compact slots. Consumer DP
// (probability domain, per-lane power-of-2 frames) unchanged.

#define B_      256
#define T_      512
#define V_      256
#define L_      64
#define BLANK_  (V_ - 1)
#define EPS_    1e-7f
#define FULL_   0xffffffffu
#define CHUNK   8
#define RING    8
#define NCHUNK  (T_ / CHUNK)   // 64

// per-pair dynamic smem region (floats)
#define ROW_FLOATS   (RING * CHUNK * V_)             // 16384 floats = 64KB
#define C2_OFF       ROW_FLOATS                      // float2[4][CHUNK][32]
#define C2_FLOATS    (4 * CHUNK * 32 * 2)            // 2048 floats = 8KB
#define CB_OFF       (C2_OFF + C2_FLOATS)            // float[4][CHUNK]
#define PAIR_FLOATS  (ROW_FLOATS + C2_FLOATS + 4 * CHUNK)
#define SMEM_BYTES   (2 * PAIR_FLOATS * 4)

__device__ __forceinline__ uint32_t smem_u32(const void* p) {
    return (uint32_t)__cvta_generic_to_shared(p);
}
__device__ __forceinline__ void cpa16(uint32_t s, const float* g) {
    asm volatile("cp.async.cg.shared.global [%0], [%1], 16;" :: "r"(s), "l"(g));
}
__device__ __forceinline__ void cpa_commit() {
    asm volatile("cp.async.commit_group;" ::: "memory");
}
__device__ __forceinline__ void cpa_wait(int n) {
    switch (n) {
      case 0: asm volatile("cp.async.wait_group 0;" ::: "memory"); break;
      case 1: asm volatile("cp.async.wait_group 1;" ::: "memory"); break;
      case 2: asm volatile("cp.async.wait_group 2;" ::: "memory"); break;
      case 3: asm volatile("cp.async.wait_group 3;" ::: "memory"); break;
      case 4: asm volatile("cp.async.wait_group 4;" ::: "memory"); break;
      case 5: asm volatile("cp.async.wait_group 5;" ::: "memory"); break;
      default: asm volatile("cp.async.wait_group 6;" ::: "memory"); break;
    }
}
__device__ __forceinline__ void barrier_pair(int pair) {
    asm volatile("bar.sync %0, 64;" :: "r"(pair + 1) : "memory");
}
__device__ __forceinline__ float exp2i_clamped(int k) {
    k = max(-126, min(127, k));
    return __int_as_float((k + 127) << 23);
}
__device__ __forceinline__ int expo(float m) {
    return ((__float_as_int(m) >> 23) & 0xff) - 127;
}

__global__ __launch_bounds__(128)
void ctc_kernel(const int* __restrict__ y_true,
                const float* __restrict__ y_pred,
                float* __restrict__ out)
{
    extern __shared__ float dsm[];

    const int lane = threadIdx.x & 31;
    const int warp = threadIdx.x >> 5;
    const int pair = warp & 1;
    const bool is_producer = (warp >= 2);

    const int b = blockIdx.x * 2 + pair;

    float*  const PR   = dsm + pair * PAIR_FLOATS;
    float*  const ROWp = PR;                        // [RING][CHUNK][V_] (compacted cols)
    float2* const C2   = (float2*)(PR + C2_OFF);    // [4][CHUNK][32]
    float*  const CB   = PR + CB_OFF;               // [4][CHUNK]

    const float* __restrict__ base = y_pred + (size_t)b * (T_ * V_);
    const uint32_t sROW = smem_u32(ROWp);

    const int lab0 = y_true[b * L_ + 2 * lane];
    const int lab1 = y_true[b * L_ + 2 * lane + 1];

    if (is_producer) {
        // ================= PRODUCER =================
        // needed-sector mask (32 sectors of 8 floats each; blank in sector 31)
        unsigned need = (1u << (lab0 >> 3)) | (1u << (lab1 >> 3));
        need = __reduce_or_sync(FULL_, need) | 0x80000000u;
        const int nsec = __popc(need);
        // lane's sector = position of the lane-th set bit
        unsigned mm = need;
        for (int i = 0; i < lane; i++) mm &= (mm - 1);
        const int  mysec  = __ffs(mm) - 1;
        const bool active = (lane < nsec);
        // compacted in-row offsets (floats) for the gather stage
        const int o0 = __popc(need & ((1u << (lab0 >> 3)) - 1)) * 8 + (lab0 & 7);
        const int o1 = __popc(need & ((1u << (lab1 >> 3)) - 1)) * 8 + (lab1 & 7);
        const int ob = (nsec - 1) * 8 + 7;   // blank: last compact sector, offset 7

#define ISSUE(c) do {                                                     \
        const int _slot = (c) & (RING - 1);                               \
        const float* _g = base + (c) * (CHUNK * V_) + mysec * 8;          \
        const uint32_t _dst = sROW + _slot * (CHUNK * V_ * 4) + lane*32;  \
        _Pragma("unroll")                                                 \
        for (int _i = 0; _i < CHUNK; _i++) {                              \
            if (active) {                                                 \
                cpa16(_dst + _i * (V_ * 4) + 0,  _g + _i * V_);           \
                cpa16(_dst + _i * (V_ * 4) + 16, _g + _i * V_ + 4);       \
            }                                                             \
        }                                                                 \
        cpa_commit();                                                     \
    } while (0)

#define PGATHER(c) do {                                                   \
        const int _rs = (c) & (RING - 1), _cs = (c) & 3;                  \
        const float* _rb = ROWp + _rs * (CHUNK * V_);                     \
        float _v1[CHUNK], _v3[CHUNK];                                     \
        _Pragma("unroll")                                                 \
        for (int _i = 0; _i < CHUNK; _i++) {                              \
            _v1[_i] = _rb[_i * V_ + o0];                                  \
            _v3[_i] = _rb[_i * V_ + o1];                                  \
        }                                                                 \
        _Pragma("unroll")                                                 \
        for (int _i = 0; _i < CHUNK; _i++)                                \
            C2[(_cs * CHUNK + _i) * 32 + lane] = make_float2(_v1[_i], _v3[_i]); \
        if (lane < CHUNK) CB[_cs * CHUNK + lane] = _rb[lane * V_ + ob];   \
    } while (0)

#pragma unroll
        for (int c = 0; c < RING - 1; c++) ISSUE(c);   // prefill 0..6

#pragma unroll 1
        for (int k = 0; k < NCHUNK / 2; k++) {
            const int c0 = 2 * k, c1 = 2 * k + 1;
            int rem = NCHUNK - 1 - c0;
            cpa_wait(rem > RING - 2 ? RING - 2 : rem);   // chunk c0 landed
            PGATHER(c0);
            if (c0 + RING - 1 < NCHUNK) ISSUE(c0 + RING - 1);
            rem = NCHUNK - 1 - c1;
            cpa_wait(rem > RING - 2 ? RING - 2 : rem);   // chunk c1 landed
            PGATHER(c1);
            if (c1 + RING - 1 < NCHUNK) ISSUE(c1 + RING - 1);
            barrier_pair(pair);                          // publish c0,c1
        }
        return;
#undef ISSUE
#undef PGATHER
    }

    // ================= CONSUMER (DP) =================
    const int labm1 = __shfl_up_sync(FULL_, lab1, 1);
    const float sk1 = (lane == 0) ? 1.0f : ((lab0 != labm1) ? 1.0f : 0.0f);
    const float sk3 = (lab1 != lab0) ? 1.0f : 0.0f;

    float a0 = 0.f, a1 = 0.f, a2 = 0.f, a3 = 0.f, a4 = 0.f;
    int   E  = 0;
    float s1 = (lane == 0) ? 0.f : 1.f, s2 = 1.f;

#define STEP(pvb, pv1, pv3) do {                                   \
        const float _pb = (pvb) + EPS_;                            \
        const float _p1 = (pv1) + EPS_;                            \
        const float _p3 = (pv3) + EPS_;                            \
        const float a3p = __shfl_up_sync(FULL_, a3, 1);            \
        const float a3q = (a3p * s1) * s2;                         \
        const float n0 = (a0 + a3q) * _pb;                         \
        const float n1 = fmaf(sk1, a3q, a0 + a1) * _p1;            \
        const float n2 = (a1 + a2) * _pb;                          \
        const float n3 = fmaf(sk3, a1, a2 + a3) * _p3;             \
        const float n4 = (a3 + a4) * _pb;                          \
        a0 = n0; a1 = n1; a2 = n2; a3 = n3; a4 = n4;               \
    } while (0)

#define NEIGHBOR_FACTORS() do {                                    \
        const int Ep = __shfl_up_sync(FULL_, E, 1);                \
        const int dE = Ep - E;                                     \
        const int d1 = dE >> 1, d2 = dE - d1;                      \
        s1 = (lane == 0) ? 0.f : exp2i_clamped(d1);                \
        s2 = exp2i_clamped(d2);                                    \
    } while (0)

#define RESCALE_SCAN() do {                                        \
        float m = fmaxf(fmaxf(a0, a1), fmaxf(a2, a3));             \
        m = fmaxf(m, a4);                                          \
        const bool nz = (m > 0.f);                                 \
        if (nz) {                                                  \
            const int e  = expo(m);                                \
            const int h1 = e >> 1, h2 = e - h1;                    \
            const float u1 = exp2i_clamped(-h1);                   \
            const float u2 = exp2i_clamped(-h2);                   \
            a0 = (a0 * u1) * u2; a1 = (a1 * u1) * u2;              \
            a2 = (a2 * u1) * u2; a3 = (a3 * u1) * u2;              \
            a4 = (a4 * u1) * u2;                                   \
            E += e;                                                \
        }                                                          \
        int key = nz ? ((lane << 15) | (E + 16384)) : -1;          \
        _Pragma("unroll")                                          \
        for (int off = 1; off < 32; off <<= 1) {                   \
            const int kl = __shfl_up_sync(FULL_, key, off);        \
            if (lane >= off) key = max(key, kl);                   \
        }                                                          \
        if (!nz) E = (key & 32767) - 16384;                        \
        NEIGHBOR_FACTORS();                                        \
    } while (0)

#define RESCALE_FAST() do {                                        \
        float m = fmaxf(fmaxf(a0, a1), fmaxf(a2, a3));             \
        m = fmaxf(m, a4);                                          \
        const int e  = expo(m);                                    \
        const int h1 = e >> 1, h2 = e - h1;                        \
        const float u1 = exp2i_clamped(-h1);                       \
        const float u2 = exp2i_clamped(-h2);                       \
        a0 = (a0 * u1) * u2; a1 = (a1 * u1) * u2;                  \
        a2 = (a2 * u1) * u2; a3 = (a3 * u1) * u2;                  \
        a4 = (a4 * u1) * u2;                                       \
        E += e;                                                    \
        NEIGHBOR_FACTORS();                                        \
    } while (0)

#define GATHERC(c, v1, v3, vb) do {                                \
        const int _cs = (c) & 3;                                   \
        _Pragma("unroll")                                          \
        for (int _i = 0; _i < CHUNK; _i++) {                       \
            const float2 _t = C2[(_cs * CHUNK + _i) * 32 + lane];  \
            (v1)[_i] = _t.x; (v3)[_i] = _t.y;                      \
            (vb)[_i] = CB[_cs * CHUNK + _i];                       \
        }                                                          \
    } while (0)

#define PROC8(v1, v3, vb) do {                                     \
        _Pragma("unroll")                                          \
        for (int _i = 0; _i < CHUNK; _i++)                         \
            STEP((vb)[_i], (v1)[_i], (v3)[_i]);                    \
    } while (0)

    float v1[CHUNK], v3[CHUNK], vb[CHUNK];

    // ---- super-chunk 0: chunks 0 (init) and 1 ----
    barrier_pair(pair);
    GATHERC(0, v1, v3, vb);
    a0 = (lane == 0) ? (vb[0] + EPS_) : 0.f;
    a1 = (lane == 0) ? (v1[0] + EPS_) : 0.f;
#pragma unroll
    for (int i = 1; i < CHUNK; i++) STEP(vb[i], v1[i], v3[i]);
    RESCALE_SCAN();
    GATHERC(1, v1, v3, vb);
    PROC8(v1, v3, vb);
    RESCALE_SCAN();

    // ---- super-chunks 1..3: frontier scan (chunks 2..7) ----
#pragma unroll 1
    for (int k = 1; k < 4; k++) {
        barrier_pair(pair);
        GATHERC(2 * k, v1, v3, vb);
        PROC8(v1, v3, vb);
        RESCALE_SCAN();
        GATHERC(2 * k + 1, v1, v3, vb);
        PROC8(v1, v3, vb);
        RESCALE_SCAN();
    }

    // ---- steady state: super-chunks 4..30 (chunks 8..61) ----
#pragma unroll 1
    for (int k = 4; k < NCHUNK / 2 - 1; k++) {
        barrier_pair(pair);
        GATHERC(2 * k, v1, v3, vb);
        PROC8(v1, v3, vb);
        RESCALE_FAST();
        GATHERC(2 * k + 1, v1, v3, vb);
        PROC8(v1, v3, vb);
        RESCALE_FAST();
    }

    // ---- last super-chunk: chunks 62, 63 ----
    barrier_pair(pair);
    GATHERC(62, v1, v3, vb);
    PROC8(v1, v3, vb);
    RESCALE_FAST();
    GATHERC(63, v1, v3, vb);
    PROC8(v1, v3, vb);

    // loss = -( log(alpha[127] + alpha[128]) + E*ln2 ), both on lane 31
    if (lane == 31) {
        const float tot = a3 + a4;
        out[b] = -(logf(tot) + (float)E * 0.6931471805599453f);
    }

#undef STEP
#undef NEIGHBOR_FACTORS
#undef RESCALE_SCAN
#undef RESCALE_FAST
#undef GATHERC
#undef PROC8
}

extern "C" void kernel_launch(void* const* d_in, const int* in_sizes, int n_in,
                              void* d_out, int out_size) {
    const int*   y_true = (const int*)  d_in[0];
    const float* y_pred = (const float*)d_in[1];
    float*       out    = (float*)      d_out;
    static bool attr_set = false;
    if (!attr_set) {
        cudaFuncSetAttribute(ctc_kernel,
                             cudaFuncAttributeMaxDynamicSharedMemorySize,
                             SMEM_BYTES);
        attr_set = true;
    }
    ctc_kernel<<<B_ / 2, 128, SMEM_BYTES>>>(y_true, y_pred, out);
}